// round 5
// baseline (speedup 1.0000x reference)
#include <cuda_runtime.h>
#include <cstdint>

#define NN 4096
#define DD 1024

// scratch (allocations are forbidden -> __device__ globals)
__device__ float g_v[(size_t)NN * DD];   // v, then vn in place
__device__ float g_rowA[NN];             // alive_i * lam_i * G * m_i/r2_i * causal_i
__device__ float g_rowR[NN];             // alive_i * (-lam_i * m_i)
__device__ float g_si[NN];
__device__ float g_sj[NN];
__device__ float g_colAlive[NN];
__device__ float g_aliveF[NN];
__device__ float g_photonF[NN];

#define BM 128
#define BN 128
#define BK 8
#define TM 8
#define TN 8

// ---------------------------------------------------------------------------
// Kernel 0: detect bool encoding (int32 / float32 / uint8) and convert to float.
// One block. 90% alive guarantees the patterns are distinguishable.
// ---------------------------------------------------------------------------
__global__ void bool_convert(const void* alive, const void* photon, int n)
{
    __shared__ int flags;   // bit0: not-all-{0,1} words; bit1: not-all-{0,1.0f} words
    if (threadIdx.x == 0) flags = 0;
    __syncthreads();
    const uint32_t* aw = (const uint32_t*)alive;
    const uint32_t* pw = (const uint32_t*)photon;
    const int nw = n / 4;   // safe under every hypothesis (smallest buffer = n bytes)
    int local = 0;
    for (int i = threadIdx.x; i < nw; i += blockDim.x) {
        uint32_t w = aw[i], q = pw[i];
        if (w > 1u || q > 1u) local |= 1;
        if (!((w == 0u || w == 0x3F800000u) && (q == 0u || q == 0x3F800000u))) local |= 2;
    }
    if (local) atomicOr(&flags, local);
    __syncthreads();
    const int f = flags;
    const int mode = ((f & 1) == 0) ? 0 : (((f & 2) == 0) ? 1 : 2);
    for (int i = threadIdx.x; i < n; i += blockDim.x) {
        float av, pv;
        if (mode == 0)      { av = ((const int*)alive)[i]     != 0   ? 1.f : 0.f;
                              pv = ((const int*)photon)[i]    != 0   ? 1.f : 0.f; }
        else if (mode == 1) { av = ((const float*)alive)[i]   != 0.f ? 1.f : 0.f;
                              pv = ((const float*)photon)[i]  != 0.f ? 1.f : 0.f; }
        else                { av = ((const uint8_t*)alive)[i] != 0   ? 1.f : 0.f;
                              pv = ((const uint8_t*)photon)[i]!= 0   ? 1.f : 0.f; }
        g_aliveF[i]  = av;
        g_photonF[i] = pv;
    }
}

// ---------------------------------------------------------------------------
// Kernel 1: C[M,Nc] = A[M,K] * B[Nc,K]^T + bias[col]   (all row-major, K-contig)
// ---------------------------------------------------------------------------
__global__ __launch_bounds__(256) void gemm_nt_bias(
    const float* __restrict__ A, const float* __restrict__ B,
    const float* __restrict__ bias, float* __restrict__ C,
    int M, int Nc, int K)
{
    __shared__ float As[BK][BM];
    __shared__ float Bs[BK][BN];

    const int tid = threadIdx.x;
    const int tx  = tid & 15;
    const int ty  = tid >> 4;
    const int rowBase = blockIdx.y * BM;
    const int colBase = blockIdx.x * BN;

    const int lr = tid >> 1;
    const int lc = (tid & 1) * 4;

    float acc[TM][TN];
#pragma unroll
    for (int m = 0; m < TM; m++)
#pragma unroll
        for (int n = 0; n < TN; n++) acc[m][n] = 0.f;

    const float* Aptr = A + (size_t)(rowBase + lr) * K + lc;
    const float* Bptr = B + (size_t)(colBase + lr) * K + lc;

    for (int kt = 0; kt < K; kt += BK) {
        float4 a4 = *reinterpret_cast<const float4*>(Aptr + kt);
        float4 b4 = *reinterpret_cast<const float4*>(Bptr + kt);
        As[lc + 0][lr] = a4.x; As[lc + 1][lr] = a4.y;
        As[lc + 2][lr] = a4.z; As[lc + 3][lr] = a4.w;
        Bs[lc + 0][lr] = b4.x; Bs[lc + 1][lr] = b4.y;
        Bs[lc + 2][lr] = b4.z; Bs[lc + 3][lr] = b4.w;
        __syncthreads();

#pragma unroll
        for (int k = 0; k < BK; k++) {
            float4 a0 = *reinterpret_cast<const float4*>(&As[k][ty * TM]);
            float4 a1 = *reinterpret_cast<const float4*>(&As[k][ty * TM + 4]);
            float4 b0 = *reinterpret_cast<const float4*>(&Bs[k][tx * TN]);
            float4 b1 = *reinterpret_cast<const float4*>(&Bs[k][tx * TN + 4]);
            float a[TM] = {a0.x, a0.y, a0.z, a0.w, a1.x, a1.y, a1.z, a1.w};
            float b[TN] = {b0.x, b0.y, b0.z, b0.w, b1.x, b1.y, b1.z, b1.w};
#pragma unroll
            for (int m = 0; m < TM; m++)
#pragma unroll
                for (int n = 0; n < TN; n++)
                    acc[m][n] = fmaf(a[m], b[n], acc[m][n]);
        }
        __syncthreads();
    }

#pragma unroll
    for (int m = 0; m < TM; m++) {
        int row = rowBase + ty * TM + m;
#pragma unroll
        for (int n = 0; n < TN; n++) {
            int col = colBase + tx * TN + n;
            C[(size_t)row * Nc + col] = acc[m][n] + bias[col];
        }
    }
}

// ---------------------------------------------------------------------------
// Kernel 2: per-row prep
// ---------------------------------------------------------------------------
__global__ __launch_bounds__(256) void row_prep(
    const float* __restrict__ vecs, const float* __restrict__ mass,
    const float* __restrict__ hops,
    const float* __restrict__ wci, const float* __restrict__ wcj,
    const float* __restrict__ log_c_p, const float* __restrict__ log_G_p)
{
    const int i = blockIdx.x;
    const int t = threadIdx.x;
    float* vrow = &g_v[(size_t)i * DD];
    const float* xrow = &vecs[(size_t)i * DD];

    float vloc[DD / 256];
    float ssv = 0.f, ssx = 0.f, si = 0.f, sj = 0.f;
#pragma unroll
    for (int k = 0; k < DD / 256; k++) {
        int d = t + k * 256;
        float v = vrow[d]; vloc[k] = v; ssv += v * v;
        float x = xrow[d];               ssx += x * x;
        si = fmaf(x, wci[d], si);
        sj = fmaf(x, wcj[d], sj);
    }
#pragma unroll
    for (int o = 16; o > 0; o >>= 1) {
        ssv += __shfl_down_sync(0xffffffffu, ssv, o);
        ssx += __shfl_down_sync(0xffffffffu, ssx, o);
        si  += __shfl_down_sync(0xffffffffu, si,  o);
        sj  += __shfl_down_sync(0xffffffffu, sj,  o);
    }
    __shared__ float sm[4][8];
    __shared__ float s_inv;
    const int warp = t >> 5, lane = t & 31;
    if (lane == 0) { sm[0][warp] = ssv; sm[1][warp] = ssx; sm[2][warp] = si; sm[3][warp] = sj; }
    __syncthreads();
    if (t == 0) {
        float tv = 0.f, txx = 0.f, tsi = 0.f, tsj = 0.f;
#pragma unroll
        for (int w = 0; w < 8; w++) { tv += sm[0][w]; txx += sm[1][w]; tsi += sm[2][w]; tsj += sm[3][w]; }
        float inv = 1.f / fmaxf(sqrtf(tv), 1e-8f);
        if (sqrtf(txx) < 1e-8f) inv = 0.f;   // zero_norm rows -> vn = 0 -> R = 0
        s_inv = inv;

        float c  = fmaxf(expf(log_c_p[0]), 1e-6f);
        float G  = expf(log_G_p[0]);
        float dl = hops[i] / c;
        float lam = (g_photonF[i] != 0.f) ? 1.f : expf(-dl);
        float rs  = fmaxf(dl, 0.1f);
        float cd  = (dl <= 1.f) ? 1.f : expf(-dl + 1.f);
        float a   = g_aliveF[i];
        g_rowA[i] = a * lam * G * mass[i] / (rs * rs) * cd;
        g_rowR[i] = -a * lam * mass[i];
        g_si[i] = tsi;
        g_sj[i] = tsj;
        g_colAlive[i] = a;
    }
    __syncthreads();
    float inv = s_inv;
#pragma unroll
    for (int k = 0; k < DD / 256; k++)
        vrow[t + k * 256] = vloc[k] * inv;
}

// ---------------------------------------------------------------------------
// Kernel 3: phi. R only for lower-triangle tiles; upper tiles skip K-loop.
// ---------------------------------------------------------------------------
__global__ __launch_bounds__(256) void phi_kernel(
    const float* __restrict__ mass, const float* __restrict__ bconf_p,
    float* __restrict__ out)
{
    __shared__ float As[BK][BM];
    __shared__ float Bs[BK][BN];

    const int tid = threadIdx.x;
    const int tx  = tid & 15;
    const int ty  = tid >> 4;
    const int rowBase = blockIdx.y * BM;
    const int colBase = blockIdx.x * BN;

    float acc[TM][TN];
#pragma unroll
    for (int m = 0; m < TM; m++)
#pragma unroll
        for (int n = 0; n < TN; n++) acc[m][n] = 0.f;

    if (blockIdx.x <= blockIdx.y) {      // tile touches j <= i: need R
        const int lr = tid >> 1;
        const int lc = (tid & 1) * 4;
        const float* Aptr = g_v + (size_t)(rowBase + lr) * DD + lc;
        const float* Bptr = g_v + (size_t)(colBase + lr) * DD + lc;
        for (int kt = 0; kt < DD; kt += BK) {
            float4 a4 = *reinterpret_cast<const float4*>(Aptr + kt);
            float4 b4 = *reinterpret_cast<const float4*>(Bptr + kt);
            As[lc + 0][lr] = a4.x; As[lc + 1][lr] = a4.y;
            As[lc + 2][lr] = a4.z; As[lc + 3][lr] = a4.w;
            Bs[lc + 0][lr] = b4.x; Bs[lc + 1][lr] = b4.y;
            Bs[lc + 2][lr] = b4.z; Bs[lc + 3][lr] = b4.w;
            __syncthreads();
#pragma unroll
            for (int k = 0; k < BK; k++) {
                float4 a0 = *reinterpret_cast<const float4*>(&As[k][ty * TM]);
                float4 a1 = *reinterpret_cast<const float4*>(&As[k][ty * TM + 4]);
                float4 b0 = *reinterpret_cast<const float4*>(&Bs[k][tx * TN]);
                float4 b1 = *reinterpret_cast<const float4*>(&Bs[k][tx * TN + 4]);
                float a[TM] = {a0.x, a0.y, a0.z, a0.w, a1.x, a1.y, a1.z, a1.w};
                float b[TN] = {b0.x, b0.y, b0.z, b0.w, b1.x, b1.y, b1.z, b1.w};
#pragma unroll
                for (int m = 0; m < TM; m++)
#pragma unroll
                    for (int n = 0; n < TN; n++)
                        acc[m][n] = fmaf(a[m], b[n], acc[m][n]);
            }
            __syncthreads();
        }
    }

    // epilogue
    const int i0 = rowBase + ty * TM;
    const int j0 = colBase + tx * TN;
    float rA[TM], rR[TM], rsi[TM];
#pragma unroll
    for (int m = 0; m < TM; m++) {
        rA[m] = g_rowA[i0 + m]; rR[m] = g_rowR[i0 + m]; rsi[m] = g_si[i0 + m];
    }
    float mj[TN], csj[TN], ca[TN];
#pragma unroll
    for (int n = 0; n < TN; n++) {
        mj[n] = mass[j0 + n]; csj[n] = g_sj[j0 + n]; ca[n] = g_colAlive[j0 + n];
    }
    const float bconf = __ldg(bconf_p);

#pragma unroll
    for (int m = 0; m < TM; m++) {
        const int i = i0 + m;
#pragma unroll
        for (int n = 0; n < TN; n++) {
            const int j = j0 + n;
            float x = rsi[m] + csj[n] + bconf;
            float conf = 1.f / (1.f + __expf(-x));
            float phi;
            if (conf > 0.8f) {
                phi = rR[m] * conf * mj[n];              // repulse (no causal mask)
            } else {
                phi = (j < i) ? rA[m] * mj[n] * fmaf(0.5f, acc[m][n], 0.5f) : 0.f;
            }
            if (i == j) phi = 0.f;
            out[(size_t)i * NN + j] = phi * ca[n];
        }
    }
}

// ---------------------------------------------------------------------------
extern "C" void kernel_launch(void* const* d_in, const int* in_sizes, int n_in,
                              void* d_out, int out_size)
{
    const float* vecs      = (const float*)d_in[0];
    const float* mass      = (const float*)d_in[1];
    const float* hops      = (const float*)d_in[2];
    const void*  alive     = d_in[3];
    const void*  is_photon = d_in[4];
    const float* W_res_w   = (const float*)d_in[5];
    const float* W_res_b   = (const float*)d_in[6];
    const float* w_conf_i  = (const float*)d_in[7];
    const float* w_conf_j  = (const float*)d_in[8];
    const float* b_conf    = (const float*)d_in[9];
    const float* log_c     = (const float*)d_in[10];
    const float* log_G     = (const float*)d_in[11];
    float* out = (float*)d_out;

    float* g_v_ptr = nullptr;
    cudaGetSymbolAddress((void**)&g_v_ptr, g_v);

    // 0) bool dtype detect + convert
    bool_convert<<<1, 256>>>(alive, is_photon, NN);

    // 1) v = vecs @ W^T + b
    dim3 g1(DD / BN, NN / BM);
    gemm_nt_bias<<<g1, 256>>>(vecs, W_res_w, W_res_b, g_v_ptr, NN, DD, DD);

    // 2) per-row prep (normalize v in place, row/col coefficients)
    row_prep<<<NN, 256>>>(vecs, mass, hops, w_conf_i, w_conf_j, log_c, log_G);

    // 3) phi
    dim3 g3(NN / BN, NN / BM);
    phi_kernel<<<g3, 256>>>(mass, b_conf, out);
}

// round 16
// speedup vs baseline: 3.5413x; 3.5413x over previous
#include <cuda_runtime.h>
#include <cuda_bf16.h>
#include <cstdint>

#define NN 4096
#define DD 1024

// ---------------------------------------------------------------------------
// scratch (device-malloc forbidden)
// ---------------------------------------------------------------------------
__device__ float         g_v[(size_t)NN * DD];      // v (fp32) from GEMM1
__device__ __nv_bfloat16 g_vecs_bf[(size_t)NN * DD];
__device__ __nv_bfloat16 g_W_bf[(size_t)DD * DD];
__device__ __nv_bfloat16 g_vn[(size_t)NN * DD];     // normalized v (bf16)
__device__ float g_rowA[NN], g_rowR[NN], g_si[NN], g_sj[NN], g_colAlive[NN];
__device__ float g_aliveF[NN], g_photonF[NN];

// ---------------------------------------------------------------------------
// portable PTX helpers (sm_80+ features only: cp.async, ldmatrix, mma.sync)
// ---------------------------------------------------------------------------
__device__ __forceinline__ uint32_t smem_u32(const void* p) {
    uint32_t a;
    asm("{ .reg .u64 t; cvta.to.shared.u64 t, %1; cvt.u32.u64 %0, t; }" : "=r"(a) : "l"(p));
    return a;
}
__device__ __forceinline__ void cp16(uint32_t s, const void* g) {
    asm volatile("cp.async.cg.shared.global [%0], [%1], 16;" :: "r"(s), "l"(g));
}
#define CP_COMMIT()  asm volatile("cp.async.commit_group;" ::: "memory")
#define CP_WAIT(n)   asm volatile("cp.async.wait_group %0;" :: "n"(n) : "memory")

__device__ __forceinline__ void ldsm_x4(uint32_t& r0, uint32_t& r1, uint32_t& r2, uint32_t& r3,
                                        uint32_t addr) {
    asm volatile("ldmatrix.sync.aligned.m8n8.x4.shared.b16 {%0,%1,%2,%3}, [%4];"
                 : "=r"(r0), "=r"(r1), "=r"(r2), "=r"(r3) : "r"(addr));
}
__device__ __forceinline__ void mma16816(float* d,
                                         uint32_t a0, uint32_t a1, uint32_t a2, uint32_t a3,
                                         uint32_t b0, uint32_t b1) {
    asm volatile("mma.sync.aligned.m16n8k16.row.col.f32.bf16.bf16.f32 "
                 "{%0,%1,%2,%3}, {%4,%5,%6,%7}, {%8,%9}, {%0,%1,%2,%3};"
                 : "+f"(d[0]), "+f"(d[1]), "+f"(d[2]), "+f"(d[3])
                 : "r"(a0), "r"(a1), "r"(a2), "r"(a3), "r"(b0), "r"(b1));
}

// smem tile: 128 rows x 128 bytes (64 bf16), SW128 swizzle
__device__ __forceinline__ uint32_t sw_addr(uint32_t base, int row, int kbyte) {
    uint32_t off = (uint32_t)(row * 128 + kbyte);
    return base + (off ^ ((off >> 3) & 0x70));
}

static constexpr int KC      = 64;       // bf16 per K-chunk (128B)
static constexpr int NCHUNK  = DD / KC;  // 16
static constexpr int TILE_B  = 128 * 128;   // 16KB per tile
static constexpr int STAGE_B = 2 * TILE_B;  // A+B per stage
static constexpr int SMEM_DYN = 2 * STAGE_B; // 64KB

// async-copy one 128x64 bf16 K-chunk into swizzled smem (256 threads, 4x16B each)
__device__ __forceinline__ void load_tile_async(const __nv_bfloat16* __restrict__ g,
                                                int kt, uint32_t sbase, int tid) {
#pragma unroll
    for (int u = 0; u < 4; u++) {
        int idx = u * 256 + tid;          // 0..1023
        int row = idx >> 3, c16 = idx & 7;
        const void* gp = g + (size_t)row * DD + kt * KC + c16 * 8;
        uint32_t off = (uint32_t)(row * 128 + c16 * 16);
        cp16(sbase + (off ^ ((off >> 3) & 0x70)), gp);
    }
}

// one K=64 chunk of the 128x128 CTA tile; warp (wm,wn) owns 32x64
__device__ __forceinline__ void compute_chunk(uint32_t sA, uint32_t sB,
                                              int wm, int wn, int lane,
                                              float acc[2][8][4]) {
    const int g = lane >> 3, r = lane & 7;
#pragma unroll
    for (int ks = 0; ks < 4; ks++) {
        const int kb = (ks * 16 + (g >> 1) * 8) * 2;   // byte col for this lane-group
        uint32_t a[2][4];
#pragma unroll
        for (int mf = 0; mf < 2; mf++) {
            int row = wm * 32 + mf * 16 + (g & 1) * 8 + r;
            ldsm_x4(a[mf][0], a[mf][1], a[mf][2], a[mf][3], sw_addr(sA, row, kb));
        }
#pragma unroll
        for (int np = 0; np < 4; np++) {   // 4 pairs of n8 fragments
            uint32_t b0, b1, b2, b3;
            int rowb = wn * 64 + np * 16 + (g & 1) * 8 + r;
            ldsm_x4(b0, b1, b2, b3, sw_addr(sB, rowb, kb));
            // b0: nfrag 2np (k lo) | b1: nfrag 2np+1 (k lo) | b2/b3: k hi
#pragma unroll
            for (int mf = 0; mf < 2; mf++) {
                mma16816(acc[mf][np * 2 + 0], a[mf][0], a[mf][1], a[mf][2], a[mf][3], b0, b2);
                mma16816(acc[mf][np * 2 + 1], a[mf][0], a[mf][1], a[mf][2], a[mf][3], b1, b3);
            }
        }
    }
}

// ---------------------------------------------------------------------------
// Kernel 0: bool dtype detect + convert (unchanged, known-good)
// ---------------------------------------------------------------------------
__global__ void bool_convert(const void* alive, const void* photon, int n)
{
    __shared__ int flags;
    if (threadIdx.x == 0) flags = 0;
    __syncthreads();
    const uint32_t* aw = (const uint32_t*)alive;
    const uint32_t* pw = (const uint32_t*)photon;
    const int nw = n / 4;
    int local = 0;
    for (int i = threadIdx.x; i < nw; i += blockDim.x) {
        uint32_t w = aw[i], q = pw[i];
        if (w > 1u || q > 1u) local |= 1;
        if (!((w == 0u || w == 0x3F800000u) && (q == 0u || q == 0x3F800000u))) local |= 2;
    }
    if (local) atomicOr(&flags, local);
    __syncthreads();
    const int f = flags;
    const int mode = ((f & 1) == 0) ? 0 : (((f & 2) == 0) ? 1 : 2);
    for (int i = threadIdx.x; i < n; i += blockDim.x) {
        float av, pv;
        if (mode == 0)      { av = ((const int*)alive)[i]      != 0   ? 1.f : 0.f;
                              pv = ((const int*)photon)[i]     != 0   ? 1.f : 0.f; }
        else if (mode == 1) { av = ((const float*)alive)[i]    != 0.f ? 1.f : 0.f;
                              pv = ((const float*)photon)[i]   != 0.f ? 1.f : 0.f; }
        else                { av = ((const uint8_t*)alive)[i]  != 0   ? 1.f : 0.f;
                              pv = ((const uint8_t*)photon)[i] != 0   ? 1.f : 0.f; }
        g_aliveF[i]  = av;
        g_photonF[i] = pv;
    }
}

// ---------------------------------------------------------------------------
// fp32 -> bf16 convert (vectorized)
// ---------------------------------------------------------------------------
__global__ void cvt_bf16(const float4* __restrict__ src, __nv_bfloat162* __restrict__ dst, int n4)
{
    int i = blockIdx.x * blockDim.x + threadIdx.x;
    if (i < n4) {
        float4 v = src[i];
        dst[2 * i]     = __floats2bfloat162_rn(v.x, v.y);
        dst[2 * i + 1] = __floats2bfloat162_rn(v.z, v.w);
    }
}

// ---------------------------------------------------------------------------
// GEMM1: g_v = vecs_bf @ W_bf^T + bias   (HMMA), grid (8, 32), 256 thr
// ---------------------------------------------------------------------------
__global__ __launch_bounds__(256) void gemm1_mma(const float* __restrict__ bias)
{
    extern __shared__ __align__(1024) char smem[];
    const uint32_t sbase = smem_u32(smem);

    const int tid  = threadIdx.x;
    const int lane = tid & 31;
    const int wrp  = tid >> 5;
    const int wm   = wrp & 3, wn = wrp >> 2;
    const int rowBase = blockIdx.y * 128;
    const int colBase = blockIdx.x * 128;

    const __nv_bfloat16* Arow = g_vecs_bf + (size_t)rowBase * DD;
    const __nv_bfloat16* Brow = g_W_bf    + (size_t)colBase * DD;

    float acc[2][8][4];
#pragma unroll
    for (int a = 0; a < 2; a++)
#pragma unroll
        for (int b = 0; b < 8; b++)
#pragma unroll
            for (int c = 0; c < 4; c++) acc[a][b][c] = 0.f;

    load_tile_async(Arow, 0, sbase, tid);
    load_tile_async(Brow, 0, sbase + TILE_B, tid);
    CP_COMMIT();

    for (int kt = 0; kt < NCHUNK; kt++) {
        const uint32_t cur = sbase + (kt & 1) * STAGE_B;
        if (kt + 1 < NCHUNK) {
            const uint32_t nxt = sbase + ((kt + 1) & 1) * STAGE_B;
            load_tile_async(Arow, kt + 1, nxt, tid);
            load_tile_async(Brow, kt + 1, nxt + TILE_B, tid);
            CP_COMMIT();
            CP_WAIT(1);
        } else {
            CP_WAIT(0);
        }
        __syncthreads();
        compute_chunk(cur, cur + TILE_B, wm, wn, lane, acc);
        __syncthreads();
    }

    // epilogue: acc + bias -> g_v
#pragma unroll
    for (int mf = 0; mf < 2; mf++) {
        const int m = rowBase + wm * 32 + mf * 16 + (lane >> 2);
#pragma unroll
        for (int nf = 0; nf < 8; nf++) {
            const int n = colBase + wn * 64 + nf * 8 + (lane & 3) * 2;
            const float* d = acc[mf][nf];
            float2 o0 = { d[0] + bias[n], d[1] + bias[n + 1] };
            float2 o1 = { d[2] + bias[n], d[3] + bias[n + 1] };
            *reinterpret_cast<float2*>(g_v + (size_t)m * DD + n)       = o0;
            *reinterpret_cast<float2*>(g_v + (size_t)(m + 8) * DD + n) = o1;
        }
    }
}

// ---------------------------------------------------------------------------
// row_prep: norms, si/sj, row coefficients; writes vn as bf16 (unchanged)
// ---------------------------------------------------------------------------
__global__ __launch_bounds__(256) void row_prep(
    const float* __restrict__ vecs, const float* __restrict__ mass,
    const float* __restrict__ hops,
    const float* __restrict__ wci, const float* __restrict__ wcj,
    const float* __restrict__ log_c_p, const float* __restrict__ log_G_p)
{
    const int i = blockIdx.x;
    const int t = threadIdx.x;

    const float4 v4  = *reinterpret_cast<const float4*>(g_v  + (size_t)i * DD + 4 * t);
    const float4 x4  = *reinterpret_cast<const float4*>(vecs + (size_t)i * DD + 4 * t);
    const float4 wi4 = *reinterpret_cast<const float4*>(wci + 4 * t);
    const float4 wj4 = *reinterpret_cast<const float4*>(wcj + 4 * t);

    float ssv = v4.x * v4.x + v4.y * v4.y + v4.z * v4.z + v4.w * v4.w;
    float ssx = x4.x * x4.x + x4.y * x4.y + x4.z * x4.z + x4.w * x4.w;
    float si  = x4.x * wi4.x + x4.y * wi4.y + x4.z * wi4.z + x4.w * wi4.w;
    float sj  = x4.x * wj4.x + x4.y * wj4.y + x4.z * wj4.z + x4.w * wj4.w;

#pragma unroll
    for (int o = 16; o > 0; o >>= 1) {
        ssv += __shfl_down_sync(0xffffffffu, ssv, o);
        ssx += __shfl_down_sync(0xffffffffu, ssx, o);
        si  += __shfl_down_sync(0xffffffffu, si,  o);
        sj  += __shfl_down_sync(0xffffffffu, sj,  o);
    }
    __shared__ float sm[4][8];
    __shared__ float s_inv;
    const int warp = t >> 5, lane = t & 31;
    if (lane == 0) { sm[0][warp] = ssv; sm[1][warp] = ssx; sm[2][warp] = si; sm[3][warp] = sj; }
    __syncthreads();
    if (t == 0) {
        float tv = 0.f, txx = 0.f, tsi = 0.f, tsj = 0.f;
#pragma unroll
        for (int w = 0; w < 8; w++) { tv += sm[0][w]; txx += sm[1][w]; tsi += sm[2][w]; tsj += sm[3][w]; }
        float inv = 1.f / fmaxf(sqrtf(tv), 1e-8f);
        if (sqrtf(txx) < 1e-8f) inv = 0.f;
        s_inv = inv;

        float c  = fmaxf(expf(log_c_p[0]), 1e-6f);
        float G  = expf(log_G_p[0]);
        float dl = hops[i] / c;
        float lam = (g_photonF[i] != 0.f) ? 1.f : expf(-dl);
        float rs  = fmaxf(dl, 0.1f);
        float cd  = (dl <= 1.f) ? 1.f : expf(-dl + 1.f);
        float a   = g_aliveF[i];
        g_rowA[i] = a * lam * G * mass[i] / (rs * rs) * cd;
        g_rowR[i] = -a * lam * mass[i];
        g_si[i] = tsi;
        g_sj[i] = tsj;
        g_colAlive[i] = a;
    }
    __syncthreads();
    const float inv = s_inv;
    __nv_bfloat162* d = reinterpret_cast<__nv_bfloat162*>(g_vn + (size_t)i * DD + 4 * t);
    d[0] = __floats2bfloat162_rn(v4.x * inv, v4.y * inv);
    d[1] = __floats2bfloat162_rn(v4.z * inv, v4.w * inv);
}

// ---------------------------------------------------------------------------
// phi: HMMA R-GEMM on lower-triangle tiles + fused epilogue; upper tiles are
// epilogue-only. grid (32, 32), 256 thr
// ---------------------------------------------------------------------------
__global__ __launch_bounds__(256) void phi_mma(
    const float* __restrict__ mass, const float* __restrict__ bconf_p,
    float* __restrict__ out)
{
    extern __shared__ __align__(1024) char smem[];
    const uint32_t sbase = smem_u32(smem);
    __shared__ float s_rA[128], s_rR[128], s_rsi[128];
    __shared__ float s_mj[128], s_csj[128], s_ca[128];

    const int tid  = threadIdx.x;
    const int lane = tid & 31;
    const int wrp  = tid >> 5;
    const int wm   = wrp & 3, wn = wrp >> 2;
    const int rowBase = blockIdx.y * 128;
    const int colBase = blockIdx.x * 128;
    const bool lower = (blockIdx.x <= blockIdx.y);

    if (tid < 128) {
        const int i = rowBase + tid;
        s_rA[tid] = g_rowA[i]; s_rR[tid] = g_rowR[i]; s_rsi[tid] = g_si[i];
    } else {
        const int j = colBase + tid - 128;
        s_mj[tid - 128] = mass[j]; s_csj[tid - 128] = g_sj[j]; s_ca[tid - 128] = g_colAlive[j];
    }

    float acc[2][8][4];
#pragma unroll
    for (int a = 0; a < 2; a++)
#pragma unroll
        for (int b = 0; b < 8; b++)
#pragma unroll
            for (int c = 0; c < 4; c++) acc[a][b][c] = 0.f;

    if (lower) {
        const __nv_bfloat16* Arow = g_vn + (size_t)rowBase * DD;
        const __nv_bfloat16* Brow = g_vn + (size_t)colBase * DD;
        load_tile_async(Arow, 0, sbase, tid);
        load_tile_async(Brow, 0, sbase + TILE_B, tid);
        CP_COMMIT();

        for (int kt = 0; kt < NCHUNK; kt++) {
            const uint32_t cur = sbase + (kt & 1) * STAGE_B;
            if (kt + 1 < NCHUNK) {
                const uint32_t nxt = sbase + ((kt + 1) & 1) * STAGE_B;
                load_tile_async(Arow, kt + 1, nxt, tid);
                load_tile_async(Brow, kt + 1, nxt + TILE_B, tid);
                CP_COMMIT();
                CP_WAIT(1);
            } else {
                CP_WAIT(0);
            }
            __syncthreads();
            compute_chunk(cur, cur + TILE_B, wm, wn, lane, acc);
            __syncthreads();
        }
    } else {
        __syncthreads();   // make staged row/col arrays visible
    }

    // fused epilogue
    const float bconf = __ldg(bconf_p);
#pragma unroll
    for (int mf = 0; mf < 2; mf++) {
        const int ml = wm * 32 + mf * 16 + (lane >> 2);   // local row (and +8)
#pragma unroll
        for (int nf = 0; nf < 8; nf++) {
            const int nl = wn * 64 + nf * 8 + (lane & 3) * 2;  // local col (and +1)
            const float* d = acc[mf][nf];
#pragma unroll
            for (int h = 0; h < 2; h++) {          // row half: ml or ml+8
                const int il = ml + h * 8;
                const int i  = rowBase + il;
                float2 o;
#pragma unroll
                for (int q = 0; q < 2; q++) {      // two adjacent cols
                    const int jl = nl + q;
                    const int j  = colBase + jl;
                    float x = s_rsi[il] + s_csj[jl] + bconf;
                    float conf = 1.f / (1.f + __expf(-x));
                    float mj = s_mj[jl];
                    float p;
                    if (conf > 0.8f) {
                        p = s_rR[il] * conf * mj;
                    } else {
                        p = (j < i) ? s_rA[il] * mj * fmaf(0.5f, d[h * 2 + q], 0.5f) : 0.f;
                    }
                    if (i == j) p = 0.f;
                    (q == 0 ? o.x : o.y) = p * s_ca[jl];
                }
                *reinterpret_cast<float2*>(out + (size_t)i * NN + colBase + nl) = o;
            }
        }
    }
}

// ---------------------------------------------------------------------------
extern "C" void kernel_launch(void* const* d_in, const int* in_sizes, int n_in,
                              void* d_out, int out_size)
{
    const float* vecs      = (const float*)d_in[0];
    const float* mass      = (const float*)d_in[1];
    const float* hops      = (const float*)d_in[2];
    const void*  alive     = d_in[3];
    const void*  is_photon = d_in[4];
    const float* W_res_w   = (const float*)d_in[5];
    const float* W_res_b   = (const float*)d_in[6];
    const float* w_conf_i  = (const float*)d_in[7];
    const float* w_conf_j  = (const float*)d_in[8];
    const float* b_conf    = (const float*)d_in[9];
    const float* log_c     = (const float*)d_in[10];
    const float* log_G     = (const float*)d_in[11];
    float* out = (float*)d_out;

    __nv_bfloat162* vecs_bf2 = nullptr; cudaGetSymbolAddress((void**)&vecs_bf2, g_vecs_bf);
    __nv_bfloat162* W_bf2    = nullptr; cudaGetSymbolAddress((void**)&W_bf2,    g_W_bf);

    cudaFuncSetAttribute(gemm1_mma, cudaFuncAttributeMaxDynamicSharedMemorySize, SMEM_DYN);
    cudaFuncSetAttribute(phi_mma,   cudaFuncAttributeMaxDynamicSharedMemorySize, SMEM_DYN);

    // 0) bool dtype detect + convert
    bool_convert<<<1, 256>>>(alive, is_photon, NN);

    // 1) fp32 -> bf16 conversions
    cvt_bf16<<<(NN * DD / 4 + 255) / 256, 256>>>((const float4*)vecs,    vecs_bf2, NN * DD / 4);
    cvt_bf16<<<(DD * DD / 4 + 255) / 256, 256>>>((const float4*)W_res_w, W_bf2,    DD * DD / 4);

    // 2) v = vecs @ W^T + b   (HMMA)
    gemm1_mma<<<dim3(DD / 128, NN / 128), 256, SMEM_DYN>>>(W_res_b);

    // 3) per-row prep (writes bf16 vn + row/col coefficients)
    row_prep<<<NN, 256>>>(vecs, mass, hops, w_conf_i, w_conf_j, log_c, log_G);

    // 4) phi (HMMA on lower triangle + fused epilogue)
    phi_mma<<<dim3(NN / 128, NN / 128), 256, SMEM_DYN>>>(mass, b_conf, out);
}